// round 1
// baseline (speedup 1.0000x reference)
#include <cuda_runtime.h>
#include <mma.h>
#include <math.h>

using namespace nvcuda;

#define DM   1024
#define NB   4
#define SQ   4096

// Scratch (device globals: the sanctioned alloc-free workaround)
__device__ float g_q[(size_t)NB * SQ * DM];
__device__ float g_k[(size_t)NB * SQ * DM];
__device__ float g_v[(size_t)NB * SQ * DM];
__device__ float g_s[(size_t)NB * SQ * SQ];

// ---------------------------------------------------------------------------
// C = alpha * A(M,K) * B(N,K)^T   (both row-major, K contiguous)
// PRECISE=true  -> 3xTF32 (hi/lo mantissa split, ~fp32 accuracy)
// PRECISE=false -> plain TF32
// Tile: BM=BN=64, BK=32, 128 threads (4 warps, 2x2 warp grid, 32x32 per warp)
// ---------------------------------------------------------------------------
template <bool PRECISE>
__global__ void __launch_bounds__(128) gemm_abT_kernel(
    const float* __restrict__ Ab, const float* __restrict__ Bb,
    float* __restrict__ Cb, int N, int K,
    long sA, long sB, long sC, float alpha)
{
    constexpr int BM = 64, BN = 64, BK = 32;
    const float* A = Ab + (long)blockIdx.z * sA;
    const float* B = Bb + (long)blockIdx.z * sB;
    float*       C = Cb + (long)blockIdx.z * sC;

    __shared__ float As[BM][BK + 4];
    __shared__ float Bs[BN][BK + 4];

    const int tm   = blockIdx.y * BM;
    const int tn   = blockIdx.x * BN;
    const int warp = threadIdx.x >> 5;
    const int wm   = (warp >> 1) * 32;
    const int wn   = (warp & 1) * 32;

    wmma::fragment<wmma::accumulator, 16, 16, 8, float> acc[2][2];
#pragma unroll
    for (int i = 0; i < 2; i++)
#pragma unroll
        for (int j = 0; j < 2; j++) wmma::fill_fragment(acc[i][j], 0.0f);

    for (int kk = 0; kk < K; kk += BK) {
#pragma unroll
        for (int t = threadIdx.x; t < BM * BK / 4; t += 128) {
            int r = t >> 3;            // BK/4 == 8 float4 per row
            int c = (t & 7) << 2;
            *(float4*)&As[r][c] = *(const float4*)&A[(long)(tm + r) * K + kk + c];
            *(float4*)&Bs[r][c] = *(const float4*)&B[(long)(tn + r) * K + kk + c];
        }
        __syncthreads();

#pragma unroll
        for (int ks = 0; ks < BK; ks += 8) {
            wmma::fragment<wmma::matrix_a, 16, 16, 8, wmma::precision::tf32, wmma::row_major> ah[2], al[2];
            wmma::fragment<wmma::matrix_b, 16, 16, 8, wmma::precision::tf32, wmma::col_major> bh[2], bl[2];
#pragma unroll
            for (int i = 0; i < 2; i++) {
                wmma::load_matrix_sync(ah[i], &As[wm + i * 16][ks], BK + 4);
                if (PRECISE) {
#pragma unroll
                    for (int e = 0; e < ah[i].num_elements; e++) {
                        float x = ah[i].x[e];
                        float h = wmma::__float_to_tf32(x);
                        ah[i].x[e] = h;
                        al[i].x[e] = wmma::__float_to_tf32(x - h);
                    }
                } else {
#pragma unroll
                    for (int e = 0; e < ah[i].num_elements; e++)
                        ah[i].x[e] = wmma::__float_to_tf32(ah[i].x[e]);
                }
            }
#pragma unroll
            for (int j = 0; j < 2; j++) {
                wmma::load_matrix_sync(bh[j], &Bs[wn + j * 16][ks], BK + 4);
                if (PRECISE) {
#pragma unroll
                    for (int e = 0; e < bh[j].num_elements; e++) {
                        float x = bh[j].x[e];
                        float h = wmma::__float_to_tf32(x);
                        bh[j].x[e] = h;
                        bl[j].x[e] = wmma::__float_to_tf32(x - h);
                    }
                } else {
#pragma unroll
                    for (int e = 0; e < bh[j].num_elements; e++)
                        bh[j].x[e] = wmma::__float_to_tf32(bh[j].x[e]);
                }
            }
#pragma unroll
            for (int i = 0; i < 2; i++)
#pragma unroll
                for (int j = 0; j < 2; j++) {
                    if (PRECISE) {
                        wmma::mma_sync(acc[i][j], ah[i], bl[j], acc[i][j]);
                        wmma::mma_sync(acc[i][j], al[i], bh[j], acc[i][j]);
                    }
                    wmma::mma_sync(acc[i][j], ah[i], bh[j], acc[i][j]);
                }
        }
        __syncthreads();
    }

#pragma unroll
    for (int i = 0; i < 2; i++)
#pragma unroll
        for (int j = 0; j < 2; j++) {
#pragma unroll
            for (int e = 0; e < acc[i][j].num_elements; e++) acc[i][j].x[e] *= alpha;
            wmma::store_matrix_sync(&C[(long)(tm + wm + i * 16) * N + tn + wn + j * 16],
                                    acc[i][j], N, wmma::mem_row_major);
        }
}

// ---------------------------------------------------------------------------
// C = A(M,K) * B(K,N)   (row-major). Plain TF32.
// ---------------------------------------------------------------------------
__global__ void __launch_bounds__(128) gemm_ab_kernel(
    const float* __restrict__ Ab, const float* __restrict__ Bb,
    float* __restrict__ Cb, int N, int K,
    long sA, long sB, long sC)
{
    constexpr int BM = 64, BN = 64, BK = 32;
    const float* A = Ab + (long)blockIdx.z * sA;
    const float* B = Bb + (long)blockIdx.z * sB;
    float*       C = Cb + (long)blockIdx.z * sC;

    __shared__ float As[BM][BK + 4];
    __shared__ float Bs[BK][BN + 4];

    const int tm   = blockIdx.y * BM;
    const int tn   = blockIdx.x * BN;
    const int warp = threadIdx.x >> 5;
    const int wm   = (warp >> 1) * 32;
    const int wn   = (warp & 1) * 32;

    wmma::fragment<wmma::accumulator, 16, 16, 8, float> acc[2][2];
#pragma unroll
    for (int i = 0; i < 2; i++)
#pragma unroll
        for (int j = 0; j < 2; j++) wmma::fill_fragment(acc[i][j], 0.0f);

    for (int kk = 0; kk < K; kk += BK) {
#pragma unroll
        for (int t = threadIdx.x; t < BM * BK / 4; t += 128) {
            int r = t >> 3;
            int c = (t & 7) << 2;
            *(float4*)&As[r][c] = *(const float4*)&A[(long)(tm + r) * K + kk + c];
        }
#pragma unroll
        for (int t = threadIdx.x; t < BK * BN / 4; t += 128) {
            int r = t >> 4;            // BN/4 == 16 float4 per row
            int c = (t & 15) << 2;
            *(float4*)&Bs[r][c] = *(const float4*)&B[(long)(kk + r) * N + tn + c];
        }
        __syncthreads();

#pragma unroll
        for (int ks = 0; ks < BK; ks += 8) {
            wmma::fragment<wmma::matrix_a, 16, 16, 8, wmma::precision::tf32, wmma::row_major> af[2];
            wmma::fragment<wmma::matrix_b, 16, 16, 8, wmma::precision::tf32, wmma::row_major> bf[2];
#pragma unroll
            for (int i = 0; i < 2; i++) {
                wmma::load_matrix_sync(af[i], &As[wm + i * 16][ks], BK + 4);
#pragma unroll
                for (int e = 0; e < af[i].num_elements; e++)
                    af[i].x[e] = wmma::__float_to_tf32(af[i].x[e]);
            }
#pragma unroll
            for (int j = 0; j < 2; j++) {
                wmma::load_matrix_sync(bf[j], &Bs[ks][wn + j * 16], BN + 4);
#pragma unroll
                for (int e = 0; e < bf[j].num_elements; e++)
                    bf[j].x[e] = wmma::__float_to_tf32(bf[j].x[e]);
            }
#pragma unroll
            for (int i = 0; i < 2; i++)
#pragma unroll
                for (int j = 0; j < 2; j++)
                    wmma::mma_sync(acc[i][j], af[i], bf[j], acc[i][j]);
        }
        __syncthreads();
    }

#pragma unroll
    for (int i = 0; i < 2; i++)
#pragma unroll
        for (int j = 0; j < 2; j++)
            wmma::store_matrix_sync(&C[(long)(tm + wm + i * 16) * N + tn + wn + j * 16],
                                    acc[i][j], N, wmma::mem_row_major);
}

// ---------------------------------------------------------------------------
// In-place row softmax over 4096-wide rows. One block (256 thr) per row.
// ---------------------------------------------------------------------------
__global__ void __launch_bounds__(256) softmax_kernel(float* __restrict__ Sg)
{
    float* row = Sg + (size_t)blockIdx.x * SQ;
    const int tid = threadIdx.x;
    __shared__ float red[8];

    float vals[16];
    float m = -3.4e38f;
#pragma unroll
    for (int i = 0; i < 16; i++) {
        vals[i] = row[tid + i * 256];
        m = fmaxf(m, vals[i]);
    }
#pragma unroll
    for (int o = 16; o; o >>= 1) m = fmaxf(m, __shfl_xor_sync(0xffffffffu, m, o));
    if ((tid & 31) == 0) red[tid >> 5] = m;
    __syncthreads();
    {
        float t = red[tid & 7];
#pragma unroll
        for (int o = 4; o; o >>= 1) t = fmaxf(t, __shfl_xor_sync(0xffffffffu, t, o));
        m = t;
    }

    float sum = 0.0f;
#pragma unroll
    for (int i = 0; i < 16; i++) {
        vals[i] = __expf(vals[i] - m);
        sum += vals[i];
    }
#pragma unroll
    for (int o = 16; o; o >>= 1) sum += __shfl_xor_sync(0xffffffffu, sum, o);
    __syncthreads();               // red reuse
    if ((tid & 31) == 0) red[tid >> 5] = sum;
    __syncthreads();
    {
        float t = red[tid & 7];
#pragma unroll
        for (int o = 4; o; o >>= 1) t += __shfl_xor_sync(0xffffffffu, t, o);
        sum = t;
    }

    float inv = 1.0f / sum;
#pragma unroll
    for (int i = 0; i < 16; i++) row[tid + i * 256] = vals[i] * inv;
}

// ---------------------------------------------------------------------------
extern "C" void kernel_launch(void* const* d_in, const int* in_sizes, int n_in,
                              void* d_out, int out_size)
{
    const float* x  = (const float*)d_in[0];   // (4, 4096, 1024)
    const float* Wq = (const float*)d_in[1];   // (1024, 1024)
    const float* Wk = (const float*)d_in[2];
    const float* Wv = (const float*)d_in[3];
    float* out = (float*)d_out;                // (4, 4096, 1024) fp32

    float *q, *k, *v, *s;
    cudaGetSymbolAddress((void**)&q, g_q);
    cudaGetSymbolAddress((void**)&k, g_k);
    cudaGetSymbolAddress((void**)&v, g_v);
    cudaGetSymbolAddress((void**)&s, g_s);

    const dim3 blk(128);

    // Phase 1: QKV projections (3xTF32 for ~fp32 accuracy). M = 4*4096 = 16384.
    {
        dim3 grid(DM / 64, (NB * SQ) / 64, 1);
        gemm_abT_kernel<true><<<grid, blk>>>(x, Wq, q, DM, DM, 0, 0, 0, 1.0f);
        gemm_abT_kernel<true><<<grid, blk>>>(x, Wk, k, DM, DM, 0, 0, 0, 1.0f);
        gemm_abT_kernel<true><<<grid, blk>>>(x, Wv, v, DM, DM, 0, 0, 0, 1.0f);
    }

    // Phase 2: scores = (Q K^T) / 32, batched over 4 batches.
    {
        dim3 grid(SQ / 64, SQ / 64, NB);
        gemm_abT_kernel<false><<<grid, blk>>>(q, k, s, SQ, DM,
                                              (long)SQ * DM, (long)SQ * DM,
                                              (long)SQ * SQ, 1.0f / 32.0f);
    }

    // Phase 3: row softmax (in place).
    softmax_kernel<<<NB * SQ, 256>>>(s);

    // Phase 4: out = P V, batched.
    {
        dim3 grid(DM / 64, SQ / 64, NB);
        gemm_ab_kernel<<<grid, blk>>>(s, v, out, DM, SQ,
                                      (long)SQ * SQ, (long)SQ * DM,
                                      (long)SQ * DM);
    }
}